// round 2
// baseline (speedup 1.0000x reference)
#include <cuda_runtime.h>

// 2-layer GRU (B=2048, T=1024, D=64, H=32) + sigmoid head, fully fused.
// 128 CTAs x 128 thr. Each warp owns 4 batch elems; lane j owns hidden idx j.
// Weights pre-packed in smem k-quad-major (conflict-free LDS.128, reused x4);
// math via packed fp32 FMA (fma.rn.f32x2).

#define TT 1024
#define DHID 32

// shared layout in floats
#define WI0_OFF 0        // [16 quads][96] float4
#define WH0_OFF 6144     // [8 quads][96]
#define WI1_OFF 9216
#define WH1_OFF 12288
#define XB_OFF  15360    // 4 warps * 4 b * 64
#define H0B_OFF 16384    // 4 warps * 4 b * 32
#define H1B_OFF 16896
#define SMEM_FLOATS 17408
#define SMEM_BYTES (SMEM_FLOATS * 4)

typedef unsigned long long u64;

__device__ __forceinline__ u64 pk(float lo, float hi) {
    u64 r; asm("mov.b64 %0, {%1,%2};" : "=l"(r) : "f"(lo), "f"(hi)); return r;
}
__device__ __forceinline__ float hsum(u64 v) {
    float lo, hi; asm("mov.b64 {%0,%1}, %2;" : "=f"(lo), "=f"(hi) : "l"(v));
    return lo + hi;
}
__device__ __forceinline__ u64 fma2(u64 a, u64 b, u64 c) {
    u64 d; asm("fma.rn.f32x2 %0, %1, %2, %3;" : "=l"(d) : "l"(a), "l"(b), "l"(c));
    return d;
}
__device__ __forceinline__ float sig_(float v) {
    return __fdividef(1.0f, 1.0f + __expf(-v));
}
__device__ __forceinline__ float tanh_(float v) {
    v = fminf(fmaxf(v, -30.0f), 30.0f);
    float e = __expf(-2.0f * v);
    return (1.0f - e) * __fdividef(1.0f, 1.0f + e);
}

// accumulate 3 gate rows (r at lane, z at 32+lane, n at 64+lane) over KQ k-quads
// for 4 batch elems. w: [KQ][96] float4 in smem. xb: per-warp smem, stride XS.
template<int KQ, int XS>
__device__ __forceinline__ void gacc(const float4* __restrict__ w,
                                     const float* __restrict__ xb, int lane,
                                     u64 ar[4], u64 az[4], u64 an[4])
{
#pragma unroll
    for (int kq = 0; kq < KQ; kq++) {
        float4 wr = w[kq * 96 + lane];
        float4 wz = w[kq * 96 + 32 + lane];
        float4 wn = w[kq * 96 + 64 + lane];
        u64 wrl = pk(wr.x, wr.y), wrh = pk(wr.z, wr.w);
        u64 wzl = pk(wz.x, wz.y), wzh = pk(wz.z, wz.w);
        u64 wnl = pk(wn.x, wn.y), wnh = pk(wn.z, wn.w);
#pragma unroll
        for (int b = 0; b < 4; b++) {
            float4 xq = *(const float4*)(xb + b * XS + kq * 4);  // broadcast
            u64 xl = pk(xq.x, xq.y), xh = pk(xq.z, xq.w);
            ar[b] = fma2(wrl, xl, ar[b]);
            az[b] = fma2(wzl, xl, az[b]);
            an[b] = fma2(wnl, xl, an[b]);
            ar[b] = fma2(wrh, xh, ar[b]);
            az[b] = fma2(wzh, xh, az[b]);
            an[b] = fma2(wnh, xh, an[b]);
        }
    }
}

__global__ void __launch_bounds__(128, 1) gru2_fused(
    const float* __restrict__ x,
    const float* __restrict__ w_ih0, const float* __restrict__ w_hh0,
    const float* __restrict__ b_ih0, const float* __restrict__ b_hh0,
    const float* __restrict__ w_ih1, const float* __restrict__ w_hh1,
    const float* __restrict__ b_ih1, const float* __restrict__ b_hh1,
    const float* __restrict__ w_cls, const float* __restrict__ b_cls,
    float* __restrict__ out)
{
    extern __shared__ float sm[];
    const int tid = threadIdx.x, lane = tid & 31, warp = tid >> 5;

    // ---- pack weights into smem: [96][K] row-major -> [K/4][96] float4 ----
    {
        const float4* s = (const float4*)w_ih0;
        float4* d = (float4*)(sm + WI0_OFF);
        for (int i = tid; i < 96 * 16; i += 128) {
            int g = i % 96, kq = i / 96;
            d[kq * 96 + g] = s[g * 16 + kq];
        }
        const float4* s0 = (const float4*)w_hh0; float4* d0 = (float4*)(sm + WH0_OFF);
        const float4* s1 = (const float4*)w_ih1; float4* d1 = (float4*)(sm + WI1_OFF);
        const float4* s2 = (const float4*)w_hh1; float4* d2 = (float4*)(sm + WH1_OFF);
        for (int i = tid; i < 96 * 8; i += 128) {
            int g = i % 96, kq = i / 96;
            d0[kq * 96 + g] = s0[g * 8 + kq];
            d1[kq * 96 + g] = s1[g * 8 + kq];
            d2[kq * 96 + g] = s2[g * 8 + kq];
        }
        for (int i = tid; i < 1024; i += 128) sm[H0B_OFF + i] = 0.0f;  // h0b+h1b
    }
    __syncthreads();

    const int wg = blockIdx.x * 4 + warp;   // 0..511
    const int b0 = wg * 4;                  // global batch base

    float*  xbw  = sm + XB_OFF + warp * 256;
    float4* xbw4 = (float4*)xbw;
    float*  h0b  = sm + H0B_OFF + warp * 128;
    float*  h1b  = sm + H1B_OFF + warp * 128;
    const float4* wi0 = (const float4*)(sm + WI0_OFF);
    const float4* wh0 = (const float4*)(sm + WH0_OFF);
    const float4* wi1 = (const float4*)(sm + WI1_OFF);
    const float4* wh1 = (const float4*)(sm + WH1_OFF);

    // bias seeds (lo = combined bias, hi = 0)
    const u64 iA_r  = pk(b_ih0[lane]      + b_hh0[lane],      0.0f);
    const u64 iA_z  = pk(b_ih0[32 + lane] + b_hh0[32 + lane], 0.0f);
    const u64 iA_xn = pk(b_ih0[64 + lane], 0.0f);
    const u64 iA_hn = pk(b_hh0[64 + lane], 0.0f);
    const u64 iB_r  = pk(b_ih1[lane]      + b_hh1[lane],      0.0f);
    const u64 iB_z  = pk(b_ih1[32 + lane] + b_hh1[32 + lane], 0.0f);
    const u64 iB_xn = pk(b_ih1[64 + lane], 0.0f);
    const u64 iB_hn = pk(b_hh1[64 + lane], 0.0f);
    const float wclsl = w_cls[lane];
    const float bcls  = b_cls[0];

    float hA[4] = {0.f, 0.f, 0.f, 0.f};
    float hB[4] = {0.f, 0.f, 0.f, 0.f};

    // x prefetch pointers: lane covers (b = lane>>4, kq = lane&15) and (b+2, kq)
    const float4* p0 = (const float4*)x
        + (size_t)(b0 + (lane >> 4)) * (TT * 16) + (lane & 15);
    const float4* p1 = p0 + 2 * (size_t)TT * 16;
    float4 xr0 = *p0, xr1 = *p1;   // t = 0

    const int slot0 = (lane >> 4) * 16 + (lane & 15);
    const int slot1 = (2 + (lane >> 4)) * 16 + (lane & 15);

    for (int t = 0; t < TT; t++) {
        xbw4[slot0] = xr0;
        xbw4[slot1] = xr1;
        __syncwarp();
        if (t < TT - 1) { p0 += 16; p1 += 16; xr0 = *p0; xr1 = *p1; }

        // ---------- layer 0 ----------
        u64 ar[4], az[4], axn[4], ahn[4];
#pragma unroll
        for (int b = 0; b < 4; b++) { ar[b] = iA_r; az[b] = iA_z; axn[b] = iA_xn; ahn[b] = iA_hn; }
        gacc<16, 64>(wi0, xbw, lane, ar, az, axn);
        gacc<8, 32>(wh0, h0b, lane, ar, az, ahn);
        __syncwarp();   // all lanes done reading old h0b
#pragma unroll
        for (int b = 0; b < 4; b++) {
            float r = sig_(hsum(ar[b]));
            float z = sig_(hsum(az[b]));
            float n = tanh_(hsum(axn[b]) + r * hsum(ahn[b]));
            hA[b] = (1.0f - z) * n + z * hA[b];
            h0b[b * 32 + lane] = hA[b];
        }
        __syncwarp();

        // ---------- layer 1 ----------
#pragma unroll
        for (int b = 0; b < 4; b++) { ar[b] = iB_r; az[b] = iB_z; axn[b] = iB_xn; ahn[b] = iB_hn; }
        gacc<8, 32>(wi1, h0b, lane, ar, az, axn);
        gacc<8, 32>(wh1, h1b, lane, ar, az, ahn);
        __syncwarp();
#pragma unroll
        for (int b = 0; b < 4; b++) {
            float r = sig_(hsum(ar[b]));
            float z = sig_(hsum(az[b]));
            float n = tanh_(hsum(axn[b]) + r * hsum(ahn[b]));
            hB[b] = (1.0f - z) * n + z * hB[b];
            h1b[b * 32 + lane] = hB[b];
        }
        __syncwarp();
    }

    // ---------- outputs: [y (2048)] [hidden (2,2048,32)] ----------
#pragma unroll
    for (int b = 0; b < 4; b++) {
        int gb = b0 + b;
        out[2048 + gb * DHID + lane]         = hA[b];
        out[2048 + 65536 + gb * DHID + lane] = hB[b];
        float p = wclsl * hB[b];
#pragma unroll
        for (int o = 16; o > 0; o >>= 1) p += __shfl_xor_sync(0xFFFFFFFFu, p, o);
        if (lane == 0) out[gb] = sig_(p + bcls);
    }
}

extern "C" void kernel_launch(void* const* d_in, const int* in_sizes, int n_in,
                              void* d_out, int out_size)
{
    const float* x     = (const float*)d_in[0];
    const float* w_ih0 = (const float*)d_in[1];
    const float* w_hh0 = (const float*)d_in[2];
    const float* b_ih0 = (const float*)d_in[3];
    const float* b_hh0 = (const float*)d_in[4];
    const float* w_ih1 = (const float*)d_in[5];
    const float* w_hh1 = (const float*)d_in[6];
    const float* b_ih1 = (const float*)d_in[7];
    const float* b_hh1 = (const float*)d_in[8];
    const float* w_cls = (const float*)d_in[9];
    const float* b_cls = (const float*)d_in[10];
    float* out = (float*)d_out;

    cudaFuncSetAttribute(gru2_fused, cudaFuncAttributeMaxDynamicSharedMemorySize,
                         SMEM_BYTES);
    gru2_fused<<<128, 128, SMEM_BYTES>>>(x, w_ih0, w_hh0, b_ih0, b_hh0,
                                         w_ih1, w_hh1, b_ih1, b_hh1,
                                         w_cls, b_cls, out);
}